// round 1
// baseline (speedup 1.0000x reference)
#include <cuda_runtime.h>
#include <cstdint>

#define EPSV 1e-5f
#define N_MAX   163904      // >= N+1 rows (N = 160000)
#define NP_MAX  65792       // >= NPOOL+1 rows (NPOOL <= 65536)

// Persistent scratch (no allocs allowed)
__device__ float g_x1[(size_t)N_MAX * 64];
__device__ float g_x2[(size_t)N_MAX * 64];
__device__ float g_xp[(size_t)NP_MAX * 64];
__device__ float g_y3[(size_t)NP_MAX * 128];
__device__ int   g_nbr [(size_t)N_MAX * 27];
__device__ int   g_nbr2[(size_t)NP_MAX * 27];
__device__ float g_stats[768];

typedef unsigned long long u64t;

__device__ __forceinline__ u64t pack2(float a, float b) {
    u64t r; unsigned x = __float_as_uint(a), y = __float_as_uint(b);
    asm("mov.b64 %0, {%1, %2};" : "=l"(r) : "r"(x), "r"(y));
    return r;
}
__device__ __forceinline__ void fma2(u64t& d, u64t a, u64t b) {
    asm("fma.rn.f32x2 %0, %1, %2, %0;" : "+l"(d) : "l"(a), "l"(b));
}
__device__ __forceinline__ float2 unpack2(u64t v) {
    unsigned lo, hi; asm("mov.b64 {%0, %1}, %2;" : "=r"(lo), "=r"(hi) : "l"(v));
    return make_float2(__uint_as_float(lo), __uint_as_float(hi));
}

// ---------------------------------------------------------------- utilities
__global__ void fill_int_kernel(int* __restrict__ p, int n, int v) {
    int i = blockIdx.x * blockDim.x + threadIdx.x;
    if (i < n) p[i] = v;
}

__global__ void build_nbr_kernel(const int* __restrict__ km_in, const int* __restrict__ km_out,
                                 int* __restrict__ nbr, int M, int Nr) {
    int idx = blockIdx.x * blockDim.x + threadIdx.x;
    if (idx >= 27 * M) return;
    int i = km_in[idx];
    if (i < Nr) {
        int k = idx / M;
        int o = km_out[idx];
        nbr[k * Nr + o] = i;
    }
}

// ---------------------------------------------------------------- conv1: C_in=1 -> C_out=64, gather form
__global__ void __launch_bounds__(256) conv1_kernel(const float* __restrict__ feats,
                                                    const float* __restrict__ W1,
                                                    float* __restrict__ out,
                                                    const int* __restrict__ nbr, int Nr) {
    __shared__ float fs[27 * 64];
    __shared__ float ws[27 * 64];
    int t = threadIdx.x;
    int r0 = blockIdx.x * 64;
    for (int i = t; i < 27 * 64; i += 256) ws[i] = W1[i];
    for (int i = t; i < 27 * 64; i += 256) {
        int k = i >> 6, rr = i & 63, r = r0 + rr;
        float v = 0.f;
        if (r < Nr) {
            int g = nbr[k * Nr + r];
            if (g < Nr) v = feats[g];
        }
        fs[i] = v;
    }
    __syncthreads();
    int c = t & 63, rg = t >> 6;
    #pragma unroll
    for (int ri = 0; ri < 16; ri++) {
        int rr = rg * 16 + ri;
        int r = r0 + rr;
        if (r < Nr) {
            float acc = 0.f;
            #pragma unroll
            for (int k = 0; k < 27; k++) acc += fs[k * 64 + rr] * ws[k * 64 + c];
            out[(size_t)r * 64 + c] = acc;
        }
    }
}

// ---------------------------------------------------------------- conv2/conv3: gather-GEMM, 64 rows x CO per block
template<int CO>
__global__ void __launch_bounds__(256) conv_gather_kernel(const float* __restrict__ x,
                                                          const float* __restrict__ W,
                                                          float* __restrict__ out,
                                                          const int* __restrict__ nbr, int Nr) {
    constexpr int CW = CO / 16;      // floats per thread per row (4 or 8)
    __shared__ __align__(16) float Ws[64 * CO];   // Ws[j][c]
    __shared__ __align__(16) float XsT[64 * 64];  // XsT[j][rr]
    const int t  = threadIdx.x;
    const int r0 = blockIdx.x * 64;
    const int tx = t & 15, ty = t >> 4;
    const int rr = t & 63, jb = t >> 6;
    const int rowg = r0 + rr;

    u64t acc[4][CW / 2];
    #pragma unroll
    for (int i = 0; i < 4; i++)
        #pragma unroll
        for (int c = 0; c < CW / 2; c++) acc[i][c] = 0ULL;

    for (int k = 0; k < 27; k++) {
        __syncthreads();
        // load weights for this offset
        const float4* Wk = (const float4*)(W + (size_t)k * 64 * CO);
        #pragma unroll
        for (int i = 0; i < CO / 16; i++)
            ((float4*)Ws)[t + i * 256] = Wk[t + i * 256];
        // gather 64 input rows (transposed into smem)
        int g = (rowg < Nr) ? __ldg(&nbr[(size_t)k * Nr + rowg]) : Nr;  // row Nr is the zero row
        const float4* xr = (const float4*)(x + (size_t)g * 64) + jb * 4;
        #pragma unroll
        for (int q = 0; q < 4; q++) {
            float4 v = xr[q];
            int j = jb * 16 + q * 4;
            XsT[(j + 0) * 64 + rr] = v.x; XsT[(j + 1) * 64 + rr] = v.y;
            XsT[(j + 2) * 64 + rr] = v.z; XsT[(j + 3) * 64 + rr] = v.w;
        }
        __syncthreads();
        // accumulate: thread tile = 4 rows x (CW) channels, channels as pairs (2*tx+32*cc)
        #pragma unroll 4
        for (int j = 0; j < 64; j++) {
            float4 xv = ((const float4*)XsT)[j * 16 + ty];
            u64t xs0 = pack2(xv.x, xv.x), xs1 = pack2(xv.y, xv.y);
            u64t xs2 = pack2(xv.z, xv.z), xs3 = pack2(xv.w, xv.w);
            const u64t* wrow = ((const u64t*)Ws) + (size_t)j * (CO / 2) + tx;
            #pragma unroll
            for (int cc = 0; cc < CW / 2; cc++) {
                u64t wv = wrow[cc * 16];
                fma2(acc[0][cc], xs0, wv);
                fma2(acc[1][cc], xs1, wv);
                fma2(acc[2][cc], xs2, wv);
                fma2(acc[3][cc], xs3, wv);
            }
        }
    }
    // store (single write per output element, coalesced float2)
    #pragma unroll
    for (int i = 0; i < 4; i++) {
        int r = r0 + ty * 4 + i;
        if (r < Nr) {
            #pragma unroll
            for (int cc = 0; cc < CW / 2; cc++) {
                float2 f = unpack2(acc[i][cc]);
                *(float2*)(out + (size_t)r * CO + 2 * tx + 32 * cc) = f;
            }
        }
    }
}

// ---------------------------------------------------------------- BN stats + apply
template<int C>
__global__ void __launch_bounds__(256) bn_reduce_kernel(const float* __restrict__ x, int rows,
                                                        float* __restrict__ sumo, float* __restrict__ sqo) {
    constexpr int G = 256 / C;
    int t = threadIdx.x;
    int c = t & (C - 1);
    int rg = t / C;
    float s = 0.f, q = 0.f;
    for (int r = blockIdx.x * G + rg; r < rows; r += gridDim.x * G) {
        float v = x[(size_t)r * C + c];
        s += v; q = fmaf(v, v, q);
    }
    __shared__ float sh[512];
    sh[t] = s; sh[256 + t] = q;
    __syncthreads();
    if (rg == 0) {
        #pragma unroll
        for (int g = 1; g < G; g++) { s += sh[g * C + c]; q += sh[256 + g * C + c]; }
        atomicAdd(&sumo[c], s);
        atomicAdd(&sqo[c], q);
    }
}

template<int C>
__global__ void __launch_bounds__(256) bn_apply_kernel(const float* __restrict__ x, float* __restrict__ y,
                                                       int rows,
                                                       const float* __restrict__ gam, const float* __restrict__ bet,
                                                       const float* __restrict__ sums, const float* __restrict__ sqs) {
    size_t total = (size_t)rows * C;
    float invn = 1.f / (float)rows;
    for (size_t idx = (size_t)blockIdx.x * 256 + threadIdx.x; idx < total; idx += (size_t)gridDim.x * 256) {
        int c = (int)(idx & (C - 1));
        float mu = sums[c] * invn;
        float var = fmaf(-mu, mu, sqs[c] * invn);
        float scl = gam[c] * rsqrtf(var + EPSV);
        float v = fmaf(x[idx] - mu, scl, bet[c]);
        y[idx] = fmaxf(v, 0.f);
    }
}

// ---------------------------------------------------------------- maxpool (segment max), values >= 0
__global__ void __launch_bounds__(256) pool_kernel(const float* __restrict__ x, const int* __restrict__ seg,
                                                   float* __restrict__ xp, int rows) {
    size_t total = (size_t)rows * 64;
    for (size_t idx = (size_t)blockIdx.x * 256 + threadIdx.x; idx < total; idx += (size_t)gridDim.x * 256) {
        int r = (int)(idx >> 6), c = (int)(idx & 63);
        float v = x[idx];
        atomicMax((unsigned int*)&xp[(size_t)seg[r] * 64 + c], __float_as_uint(v));
    }
}

// ---------------------------------------------------------------- launch
extern "C" void kernel_launch(void* const* d_in, const int* in_sizes, int n_in,
                              void* d_out, int out_size) {
    const float* feats = (const float*)d_in[0];
    const float* W1    = (const float*)d_in[1];
    const float* g1    = (const float*)d_in[3];
    const float* be1   = (const float*)d_in[4];
    const float* W2    = (const float*)d_in[5];
    const float* g2    = (const float*)d_in[7];
    const float* be2   = (const float*)d_in[8];
    const float* W3    = (const float*)d_in[9];
    const float* g3    = (const float*)d_in[11];
    const float* be3   = (const float*)d_in[12];
    const int* km_in   = (const int*)d_in[13];
    const int* km_out  = (const int*)d_in[14];
    const int* seg     = (const int*)d_in[15];
    const int* km2_in  = (const int*)d_in[16];
    const int* km2_out = (const int*)d_in[17];

    int N  = in_sizes[0];
    int M  = in_sizes[13] / 27;
    int M2 = in_sizes[16] / 27;
    int NP = out_size / 128;

    float *x1, *x2, *xp, *y3, *stats; int *nbr, *nbr2;
    cudaGetSymbolAddress((void**)&x1, g_x1);
    cudaGetSymbolAddress((void**)&x2, g_x2);
    cudaGetSymbolAddress((void**)&xp, g_xp);
    cudaGetSymbolAddress((void**)&y3, g_y3);
    cudaGetSymbolAddress((void**)&nbr, g_nbr);
    cudaGetSymbolAddress((void**)&nbr2, g_nbr2);
    cudaGetSymbolAddress((void**)&stats, g_stats);

    // zero stats, zero rows used as gather "zero row", zero pooled buffer (max-accumulated)
    cudaMemsetAsync(stats, 0, 768 * sizeof(float), 0);
    cudaMemsetAsync(x1 + (size_t)N * 64, 0, 64 * sizeof(float), 0);
    cudaMemsetAsync(xp, 0, (size_t)(NP + 1) * 64 * sizeof(float), 0);

    // build dense neighbor tables (gather form of the kernel maps)
    fill_int_kernel<<<(27 * N + 255) / 256, 256>>>(nbr, 27 * N, N);
    build_nbr_kernel<<<(27 * M + 255) / 256, 256>>>(km_in, km_out, nbr, M, N);
    fill_int_kernel<<<(27 * NP + 255) / 256, 256>>>(nbr2, 27 * NP, NP);
    build_nbr_kernel<<<(27 * M2 + 255) / 256, 256>>>(km2_in, km2_out, nbr2, M2, NP);

    // layer 1
    conv1_kernel<<<(N + 63) / 64, 256>>>(feats, W1, x1, nbr, N);
    bn_reduce_kernel<64><<<592, 256>>>(x1, N, stats + 0, stats + 128);
    bn_apply_kernel<64><<<1184, 256>>>(x1, x1, N, g1, be1, stats + 0, stats + 128);

    // layer 2
    conv_gather_kernel<64><<<(N + 63) / 64, 256>>>(x1, W2, x2, nbr, N);
    bn_reduce_kernel<64><<<592, 256>>>(x2, N, stats + 256, stats + 384);
    bn_apply_kernel<64><<<1184, 256>>>(x2, x2, N, g2, be2, stats + 256, stats + 384);

    // maxpool
    pool_kernel<<<1184, 256>>>(x2, seg, xp, N);

    // layer 3
    conv_gather_kernel<128><<<(NP + 63) / 64, 256>>>(xp, W3, y3, nbr2, NP);
    bn_reduce_kernel<128><<<592, 256>>>(y3, NP, stats + 512, stats + 640);
    bn_apply_kernel<128><<<1184, 256>>>(y3, (float*)d_out, NP, g3, be3, stats + 512, stats + 640);
}